// round 17
// baseline (speedup 1.0000x reference)
#include <cuda_runtime.h>
#include <cuda_bf16.h>
#include <cfloat>
#include <cstdint>

// ---------------- problem constants ----------------
#define BATCH 32
#define DIM   256
#define HW    1024
#define NTOK  (BATCH*HW)              // 32768
#define KCODE 1024
#define NELEM ((size_t)BATCH*DIM*HW)  // 8388608

// ---------------- tf32 mma tiling ----------------
#define TM 128            // tokens per block
#define TN 64             // codes per block
#define NPT (KCODE/32)    // 32 partial tiles (one per 32-code half)
#define KCHUNK 16
#define NCHUNK (DIM/KCHUNK)  // 16
#define LDW (KCHUNK + 4)  // padded smem row (uint32)

// ---------------- device scratch ----------------
__device__ float  g_t1[NTOK];
__device__ float  g_s[KCODE];
__device__ int    g_idx[NTOK];
__device__ float  g_pv[NPT * NTOK];
__device__ int    g_pi[NPT * NTOK];
__device__ double g_losssum;

__device__ __forceinline__ uint32_t f2tf32(float v) {
    uint32_t r;
    asm("cvt.rna.tf32.f32 %0, %1;" : "=r"(r) : "f"(v));
    return r;
}
// exact 2-way tf32 split: v = h + m + r, |r| ~ 2^-22 |v|
__device__ __forceinline__ void split_tf32(float v, uint32_t& h, uint32_t& m) {
    h = f2tf32(v);
    float r = v - __uint_as_float(h);   // exact (Sterbenz)
    m = f2tf32(r);
}
// permute k within groups of 8 so (c, c+4) land in adjacent slots (LDS.64)
__device__ __forceinline__ int pcol(int dd) {
    int l = dd & 7;
    return (dd & ~7) | (((l & 3) << 1) | (l >> 2));
}
__device__ __forceinline__ void mma_tf32(float* d, const uint32_t* a, const uint32_t* b) {
    asm volatile(
        "mma.sync.aligned.m16n8k8.row.col.f32.tf32.tf32.f32 "
        "{%0,%1,%2,%3}, {%4,%5,%6,%7}, {%8,%9}, {%0,%1,%2,%3};"
        : "+f"(d[0]), "+f"(d[1]), "+f"(d[2]), "+f"(d[3])
        : "r"(a[0]), "r"(a[1]), "r"(a[2]), "r"(a[3]),
          "r"(b[0]), "r"(b[1]));
}

// ============================================================
// Kernel A: prep — R2-verbatim t1, s (exact fp32, ascending d)
// ============================================================
__global__ void vq_prep_kernel(const float* __restrict__ z,
                               const float* __restrict__ emb)
{
    int tid = blockIdx.x * blockDim.x + threadIdx.x;
    if (tid == 0) g_losssum = 0.0;
    if (tid < NTOK) {
        int b = tid / HW, hw = tid % HW;
        const float* base = z + (size_t)b * DIM * HW + hw;
        float s = 0.0f;
        #pragma unroll 8
        for (int d = 0; d < DIM; d++) { float v = base[(size_t)d * HW]; s += v * v; }
        g_t1[tid] = s;
    } else if (tid < NTOK + KCODE) {
        int k = tid - NTOK;
        const float* row = emb + (size_t)k * DIM;
        float s = 0.0f;
        #pragma unroll 8
        for (int d = 0; d < DIM; d++) { float v = row[d]; s += v * v; }
        g_s[k] = s;
    }
}

// ============================================================
// Kernel B: tf32x3 THREE-PASS distance GEMM (X3 replication)
//   three separate full-K accumulators: HH, HM, MH
//   final per-element combine: (HH + HM) + MH
//   block: 128 tokens x 64 codes; warp: 32x32 (2x4 m16n8k8)
//   partials per (n-tile, wn-half) -> race-free (R12 fix)
// ============================================================
__global__ __launch_bounds__(256)
void vq_tf32_kernel(const float* __restrict__ z,
                    const float* __restrict__ emb)
{
    __shared__ uint32_t A_s[2][TM][LDW];   // [plane][token][k]
    __shared__ uint32_t B_s[2][TN][LDW];   // [plane][code][k]
    __shared__ float    s_sm[TN];

    const int tid  = threadIdx.x;
    const int lane = tid & 31;
    const int warp = tid >> 5;
    const int wm   = warp >> 1;          // 0..3  (32-token slab)
    const int wn   = warp & 1;           // 0..1  (32-code slab)
    const int g    = lane >> 2;          // group 0..7
    const int c    = lane & 3;           // 0..3

    const int t0 = blockIdx.x * TM;
    const int n0 = blockIdx.y * TN;
    const int b  = t0 / HW;
    const int hw0 = t0 % HW;             // TM divides HW
    const float* zb = z + (size_t)b * DIM * HW + hw0;

    // three independent accumulator planes: 0=HH, 1=HM, 2=MH
    float acc[3][2][4][4];
    #pragma unroll
    for (int p = 0; p < 3; p++)
        #pragma unroll
        for (int mt = 0; mt < 2; mt++)
            #pragma unroll
            for (int nt = 0; nt < 4; nt++)
                #pragma unroll
                for (int q = 0; q < 4; q++) acc[p][mt][nt][q] = 0.0f;

    for (int chunk = 0; chunk < NCHUNK; chunk++) {
        const int d0 = chunk * KCHUNK;
        __syncthreads();
        // A tile: 128 tokens x 16 dims (coalesced over tokens)
        #pragma unroll
        for (int r = 0; r < 8; r++) {
            int idx = tid + 256 * r;             // 0..2047
            int m = idx & 127, dd = idx >> 7;
            uint32_t h, mm;
            split_tf32(zb[(size_t)(d0 + dd) * HW + m], h, mm);
            int pc = pcol(dd);
            A_s[0][m][pc] = h;
            A_s[1][m][pc] = mm;
        }
        // B tile: 64 codes x 16 dims (coalesced over dims)
        #pragma unroll
        for (int r = 0; r < 4; r++) {
            int idx = tid + 256 * r;             // 0..1023
            int dd = idx & 15, n = idx >> 4;
            uint32_t h, mm;
            split_tf32(emb[(size_t)(n0 + n) * DIM + d0 + dd], h, mm);
            int pc = pcol(dd);
            B_s[0][n][pc] = h;
            B_s[1][n][pc] = mm;
        }
        __syncthreads();

        #pragma unroll
        for (int kk = 0; kk < 2; kk++) {
            const int kc = kk * 8 + 2 * c;
            uint32_t a[2][2][4];   // [plane][mt][frag]
            #pragma unroll
            for (int p = 0; p < 2; p++)
                #pragma unroll
                for (int mt = 0; mt < 2; mt++) {
                    uint2 lo = *(const uint2*)&A_s[p][wm * 32 + mt * 16 + g    ][kc];
                    uint2 hi = *(const uint2*)&A_s[p][wm * 32 + mt * 16 + g + 8][kc];
                    a[p][mt][0] = lo.x; a[p][mt][1] = hi.x;
                    a[p][mt][2] = lo.y; a[p][mt][3] = hi.y;
                }
            uint32_t bf[2][4][2];  // [plane][nt][frag]
            #pragma unroll
            for (int p = 0; p < 2; p++)
                #pragma unroll
                for (int nt = 0; nt < 4; nt++) {
                    uint2 bb = *(const uint2*)&B_s[p][wn * 32 + nt * 8 + g][kc];
                    bf[p][nt][0] = bb.x; bf[p][nt][1] = bb.y;
                }
            #pragma unroll
            for (int mt = 0; mt < 2; mt++)
                #pragma unroll
                for (int nt = 0; nt < 4; nt++) {
                    mma_tf32(acc[0][mt][nt], a[0][mt], bf[0][nt]);  // HH pass
                    mma_tf32(acc[1][mt][nt], a[0][mt], bf[1][nt]);  // HM pass
                    mma_tf32(acc[2][mt][nt], a[1][mt], bf[0][nt]);  // MH pass
                }
        }
    }

    // epilogue: combine passes, distances + argmin (tie -> lowest index)
    if (tid < TN) s_sm[tid] = g_s[n0 + tid];
    __syncthreads();

    const int ptile = blockIdx.y * 2 + wn;   // 0..31, ascending with code index

    #pragma unroll
    for (int mt = 0; mt < 2; mt++) {
        #pragma unroll
        for (int rh = 0; rh < 2; rh++) {
            int row = wm * 32 + mt * 16 + rh * 8 + g;
            float t1v = g_t1[t0 + row];
            float bv = FLT_MAX;
            int   bi = 0;
            #pragma unroll
            for (int nt = 0; nt < 4; nt++) {
                #pragma unroll
                for (int j = 0; j < 2; j++) {
                    int col = wn * 32 + nt * 8 + 2 * c + j;
                    int q = rh * 2 + j;
                    // X3 combine: (HH + HM) + MH, single fp32 rounding chain
                    float m = (acc[0][mt][nt][q] + acc[1][mt][nt][q]) + acc[2][mt][nt][q];
                    float dist = (t1v - 2.0f * m) + s_sm[col];
                    int idx = n0 + col;
                    if (dist < bv || (dist == bv && idx < bi)) { bv = dist; bi = idx; }
                }
            }
            // reduce across the 4 lanes of the quad (same row)
            #pragma unroll
            for (int off = 1; off < 4; off <<= 1) {
                float ov = __shfl_xor_sync(0xffffffffu, bv, off);
                int   oi = __shfl_xor_sync(0xffffffffu, bi, off);
                if (ov < bv || (ov == bv && oi < bi)) { bv = ov; bi = oi; }
            }
            if (c == 0) {
                g_pv[ptile * NTOK + t0 + row] = bv;
                g_pi[ptile * NTOK + t0 + row] = bi;
            }
        }
    }
}

// ============================================================
// Kernel B2: merge partial argmins across 32 half-tiles
// (ascending tile order == ascending code order -> lowest-index ties)
// ============================================================
__global__ void vq_merge_kernel()
{
    int t = blockIdx.x * blockDim.x + threadIdx.x;
    if (t >= NTOK) return;
    float bv = g_pv[t];
    int   bi = g_pi[t];
    #pragma unroll
    for (int nt = 1; nt < NPT; nt++) {
        float v = g_pv[nt * NTOK + t];
        if (v < bv) { bv = v; bi = g_pi[nt * NTOK + t]; }
    }
    g_idx[t] = bi;
}

// ============================================================
// Kernel C: straight-through output + loss (R3-verbatim)
// ============================================================
__global__ __launch_bounds__(256)
void vq_out_kernel(const float* __restrict__ z,
                   const float* __restrict__ emb,
                   float* __restrict__ out)
{
    size_t i = (size_t)blockIdx.x * blockDim.x + threadIdx.x;
    int hw = (int)(i & 1023);
    int d  = (int)((i >> 10) & 255);
    int b  = (int)(i >> 18);
    int t  = b * HW + hw;

    int   k    = g_idx[t];
    float zv   = z[i];
    float q    = emb[(size_t)k * DIM + d];
    float diff = q - zv;
    out[i] = zv + diff;

    double v = (double)diff * (double)diff;
    #pragma unroll
    for (int o = 16; o > 0; o >>= 1)
        v += __shfl_down_sync(0xffffffffu, v, o);

    __shared__ double ws[8];
    int lane = threadIdx.x & 31, wd = threadIdx.x >> 5;
    if (lane == 0) ws[wd] = v;
    __syncthreads();
    if (threadIdx.x == 0) {
        double s = 0.0;
        #pragma unroll
        for (int w = 0; w < 8; w++) s += ws[w];
        atomicAdd(&g_losssum, s);
    }
}

// ============================================================
// Kernel D: loss scalar
// ============================================================
__global__ void vq_loss_kernel(float* __restrict__ out, size_t loss_pos)
{
    if (threadIdx.x == 0 && blockIdx.x == 0) {
        float m = (float)(g_losssum / (double)NELEM);
        out[loss_pos] = m + 0.25f * m;
    }
}

// ============================================================
extern "C" void kernel_launch(void* const* d_in, const int* in_sizes, int n_in,
                              void* d_out, int out_size)
{
    const float* z;
    const float* emb;
    if (in_sizes[0] == (int)NELEM) {
        z = (const float*)d_in[0];
        emb = (const float*)d_in[1];
    } else {
        z = (const float*)d_in[1];
        emb = (const float*)d_in[0];
    }
    float* out = (float*)d_out;

    vq_prep_kernel<<<(NTOK + KCODE + 255) / 256, 256>>>(z, emb);

    vq_tf32_kernel<<<dim3(NTOK / TM, KCODE / TN), 256>>>(z, emb);

    vq_merge_kernel<<<NTOK / 256, 256>>>();

    vq_out_kernel<<<(int)(NELEM / 256), 256>>>(z, emb, out);

    vq_loss_kernel<<<1, 32>>>(out, (size_t)out_size - 1);
}